// round 4
// baseline (speedup 1.0000x reference)
#include <cuda_runtime.h>

constexpr int kB = 4, kS = 2048, kD = 1024, kH = 16, kDK = 64;

using u64 = unsigned long long;

__device__ __forceinline__ void fma2(u64& d, u64 a, u64 b) {
  asm("fma.rn.f32x2 %0, %1, %2, %0;" : "+l"(d) : "l"(a), "l"(b));
}
__device__ __forceinline__ void mul2(u64& d, u64 a) {
  asm("mul.rn.f32x2 %0, %0, %1;" : "+l"(d) : "l"(a));
}
__device__ __forceinline__ u64 pack2(float x, float y) {
  u64 r; asm("mov.b64 %0, {%1,%2};" : "=l"(r) : "f"(x), "f"(y)); return r;
}
__device__ __forceinline__ float2 unpack2(u64 p) {
  float x, y; asm("mov.b64 {%0,%1}, %2;" : "=f"(x), "=f"(y) : "l"(p));
  return make_float2(x, y);
}

// Scratch (device globals; allocation-free per harness rules)
__device__ float g_q [(size_t)kB * kH * kS * kDK];  // Q natural [b,h,s,dk]
__device__ float g_kt[(size_t)kB * kH * kDK * kS];  // K^T      [b,h,dk,s]
__device__ float g_v [(size_t)kB * kH * kS * kDK];  // V natural [b,h,s,dv]
__device__ float g_ao[(size_t)kB * kS * kH * kDK];  // attn out  [b,s,h*dv]

// ---------------------------------------------------------------------------
// Kernel 1: QKV projections. Tile 128(M)x64(N), 256 threads, 4x8/thread.
// A-side stored as duplicated f32 pairs (u64) -> inner loop is LDS.64+FFMA2.
// grid = (64 m-tiles, 48 = {q,k,v} x 16 heads)
// ---------------------------------------------------------------------------
__global__ __launch_bounds__(256, 3) void qkv_kernel(
    const float* __restrict__ x, const float* __restrict__ Wq,
    const float* __restrict__ Wk, const float* __restrict__ Wv) {
  __shared__ u64 As2[128 * 34];   // dup pairs [m][kk], stride 34 (16B-aligned)
  __shared__ float Bs[32 * 72];   // [kk][n] pad 72
  const int m0 = blockIdx.x * 128;
  const int mat = blockIdx.y >> 4;
  const int h = blockIdx.y & 15;
  const float* W = (mat == 0 ? Wq : (mat == 1 ? Wk : Wv)) + (size_t)h * kD * kDK;
  const int tid = threadIdx.x;
  const int ty = tid >> 3, tx = tid & 7;  // ty 0..31, tx 0..7

  u64 acc[4][4];
#pragma unroll
  for (int i = 0; i < 4; ++i)
#pragma unroll
    for (int j = 0; j < 4; ++j) acc[i][j] = 0ull;

  for (int d0 = 0; d0 < kD; d0 += 32) {
    // A tile: 128 rows x 32 kk, duplicated pairs
#pragma unroll
    for (int it = 0; it < 4; ++it) {
      int lin = tid + it * 256;
      int r = lin >> 3, dq = lin & 7;  // dq: which float4 of the 8 (32 kk)
      float4 v = *(const float4*)&x[(size_t)(m0 + r) * kD + d0 + dq * 4];
      ulonglong2* dst = (ulonglong2*)&As2[r * 34 + dq * 4];
      dst[0] = make_ulonglong2(pack2(v.x, v.x), pack2(v.y, v.y));
      dst[1] = make_ulonglong2(pack2(v.z, v.z), pack2(v.w, v.w));
    }
    // B tile: 32 kk x 64 n
#pragma unroll
    for (int it = 0; it < 2; ++it) {
      int lin = tid + it * 256;
      int kr = lin >> 4, n4 = lin & 15;
      *(float4*)&Bs[kr * 72 + n4 * 4] =
          *(const float4*)&W[(size_t)(d0 + kr) * kDK + n4 * 4];
    }
    __syncthreads();
#pragma unroll 8
    for (int kk = 0; kk < 32; ++kk) {
      ulonglong2 bA = *(const ulonglong2*)&Bs[kk * 72 + tx * 8];
      ulonglong2 bB = *(const ulonglong2*)&Bs[kk * 72 + tx * 8 + 4];
#pragma unroll
      for (int i = 0; i < 4; ++i) {
        u64 aa = As2[(ty * 4 + i) * 34 + kk];
        fma2(acc[i][0], aa, bA.x);
        fma2(acc[i][1], aa, bA.y);
        fma2(acc[i][2], aa, bB.x);
        fma2(acc[i][3], aa, bB.y);
      }
    }
    __syncthreads();
  }

  const int bh = (m0 >> 11) * kH + h;
  const int s0 = m0 & (kS - 1);
  if (mat == 1) {
    // K^T store: [b,h,dk,s]; 4 consecutive s per thread per column
#pragma unroll
    for (int j2 = 0; j2 < 4; ++j2) {
      float2 u0 = unpack2(acc[0][j2]), u1 = unpack2(acc[1][j2]);
      float2 u2 = unpack2(acc[2][j2]), u3 = unpack2(acc[3][j2]);
      int c0 = tx * 8 + 2 * j2;
      *(float4*)&g_kt[((size_t)bh * kDK + c0) * kS + s0 + ty * 4] =
          make_float4(u0.x, u1.x, u2.x, u3.x);
      *(float4*)&g_kt[((size_t)bh * kDK + c0 + 1) * kS + s0 + ty * 4] =
          make_float4(u0.y, u1.y, u2.y, u3.y);
    }
  } else {
    float* outp = (mat == 0) ? g_q : g_v;
#pragma unroll
    for (int i = 0; i < 4; ++i) {
      float2 u0 = unpack2(acc[i][0]), u1 = unpack2(acc[i][1]);
      float2 u2 = unpack2(acc[i][2]), u3 = unpack2(acc[i][3]);
      float* dp = &outp[((size_t)bh * kS + s0 + ty * 4 + i) * kDK + tx * 8];
      *(float4*)dp = make_float4(u0.x, u0.y, u1.x, u1.y);
      *(float4*)(dp + 4) = make_float4(u2.x, u2.y, u3.x, u3.y);
    }
  }
}

// ---------------------------------------------------------------------------
// Kernel 2: fused flash attention. 128q-tile, 64k K-tiles, 256 threads,
// 4q x 8dv per thread. Q in dup-pair smem; P broadcast via shfl.
// Dynamic smem: Qsd[128][66]u64 + Ks[64][72]f + Vs[64][72]f = 104448 B.
// ---------------------------------------------------------------------------
__global__ __launch_bounds__(256, 2) void attn_kernel() {
  extern __shared__ char smraw[];
  u64* Qsd = (u64*)smraw;                       // dup pairs [q][dk], stride 66
  float* Ks = (float*)(smraw + 128 * 66 * 8);   // [dk][c]  stride 72
  float* Vs = Ks + 64 * 72;                     // [c][dv]  stride 72
  const int qt = blockIdx.x, h = blockIdx.y, b = blockIdx.z;
  const int bh = b * kH + h;
  const int tid = threadIdx.x;
  const int ty = tid >> 3, tx = tid & 7;
  const int lane = tid & 31;

  const float* qsrc = g_q + ((size_t)bh * kS + qt * 128) * kDK;
#pragma unroll
  for (int it = 0; it < 8; ++it) {
    int lin = tid + it * 256;
    int r = lin >> 4, dq = lin & 15;
    float4 v = *(const float4*)&qsrc[(size_t)r * kDK + dq * 4];
    v.x *= 0.125f; v.y *= 0.125f; v.z *= 0.125f; v.w *= 0.125f;
    ulonglong2* dst = (ulonglong2*)&Qsd[r * 66 + dq * 4];
    dst[0] = make_ulonglong2(pack2(v.x, v.x), pack2(v.y, v.y));
    dst[1] = make_ulonglong2(pack2(v.z, v.z), pack2(v.w, v.w));
  }

  u64 o2[4][4];
  float m_[4], l_[4];
#pragma unroll
  for (int i = 0; i < 4; ++i) {
    m_[i] = -3.0e38f;
    l_[i] = 0.f;
#pragma unroll
    for (int j = 0; j < 4; ++j) o2[i][j] = 0ull;
  }

  const float* ktbase = g_kt + (size_t)bh * kDK * kS;
  const float* vbase = g_v + (size_t)bh * kS * kDK;

  for (int kt = 0; kt < kS / 64; ++kt) {
#pragma unroll
    for (int it = 0; it < 4; ++it) {
      int lin = tid + it * 256;
      int dd = lin >> 4, c4 = lin & 15;
      *(float4*)&Ks[dd * 72 + c4 * 4] =
          *(const float4*)&ktbase[(size_t)dd * kS + kt * 64 + c4 * 4];
    }
#pragma unroll
    for (int it = 0; it < 4; ++it) {
      int lin = tid + it * 256;
      int c = lin >> 4, dq = lin & 15;
      *(float4*)&Vs[c * 72 + dq * 4] =
          *(const float4*)&vbase[(size_t)(kt * 64 + c) * kDK + dq * 4];
    }
    __syncthreads();

    // S = Q K^T  (pairs along k-columns)
    u64 s2[4][4];
#pragma unroll
    for (int i = 0; i < 4; ++i)
#pragma unroll
      for (int j = 0; j < 4; ++j) s2[i][j] = 0ull;
#pragma unroll 8
    for (int kk = 0; kk < 64; ++kk) {
      ulonglong2 bA = *(const ulonglong2*)&Ks[kk * 72 + tx * 8];
      ulonglong2 bB = *(const ulonglong2*)&Ks[kk * 72 + tx * 8 + 4];
#pragma unroll
      for (int i = 0; i < 4; ++i) {
        u64 aa = Qsd[(ty * 4 + i) * 66 + kk];
        fma2(s2[i][0], aa, bA.x);
        fma2(s2[i][1], aa, bA.y);
        fma2(s2[i][2], aa, bB.x);
        fma2(s2[i][3], aa, bB.y);
      }
    }

    // online softmax (each row spread over the 8 tx lanes of an octet)
    float sp[4][8];
#pragma unroll
    for (int i = 0; i < 4; ++i) {
      float2 u0 = unpack2(s2[i][0]), u1 = unpack2(s2[i][1]);
      float2 u2 = unpack2(s2[i][2]), u3 = unpack2(s2[i][3]);
      float sc[8] = {u0.x, u0.y, u1.x, u1.y, u2.x, u2.y, u3.x, u3.y};
      float mx = fmaxf(fmaxf(fmaxf(sc[0], sc[1]), fmaxf(sc[2], sc[3])),
                       fmaxf(fmaxf(sc[4], sc[5]), fmaxf(sc[6], sc[7])));
      mx = fmaxf(mx, __shfl_xor_sync(0xffffffffu, mx, 1));
      mx = fmaxf(mx, __shfl_xor_sync(0xffffffffu, mx, 2));
      mx = fmaxf(mx, __shfl_xor_sync(0xffffffffu, mx, 4));
      float mnew = fmaxf(m_[i], mx);
      float corr = __expf(m_[i] - mnew);
      m_[i] = mnew;
      float sum = 0.f;
#pragma unroll
      for (int j = 0; j < 8; ++j) {
        sc[j] = __expf(sc[j] - mnew);
        sum += sc[j];
        sp[i][j] = sc[j];
      }
      sum += __shfl_xor_sync(0xffffffffu, sum, 1);
      sum += __shfl_xor_sync(0xffffffffu, sum, 2);
      sum += __shfl_xor_sync(0xffffffffu, sum, 4);
      l_[i] = l_[i] * corr + sum;
      u64 cc = pack2(corr, corr);
      mul2(o2[i][0], cc); mul2(o2[i][1], cc);
      mul2(o2[i][2], cc); mul2(o2[i][3], cc);
    }

    // O += P V  (P broadcast from registers via shfl)
    for (int ct = 0; ct < 8; ++ct) {
      int src = (lane & 24) | ct;
#pragma unroll
      for (int ci = 0; ci < 8; ++ci) {
        int c = ct * 8 + ci;
        ulonglong2 vA = *(const ulonglong2*)&Vs[c * 72 + tx * 8];
        ulonglong2 vB = *(const ulonglong2*)&Vs[c * 72 + tx * 8 + 4];
#pragma unroll
        for (int i = 0; i < 4; ++i) {
          float p = __shfl_sync(0xffffffffu, sp[i][ci], src);
          u64 pp = pack2(p, p);
          fma2(o2[i][0], pp, vA.x);
          fma2(o2[i][1], pp, vA.y);
          fma2(o2[i][2], pp, vB.x);
          fma2(o2[i][3], pp, vB.y);
        }
      }
    }
    __syncthreads();
  }

#pragma unroll
  for (int i = 0; i < 4; ++i) {
    float inv = 1.f / l_[i];
    float2 u0 = unpack2(o2[i][0]), u1 = unpack2(o2[i][1]);
    float2 u2 = unpack2(o2[i][2]), u3 = unpack2(o2[i][3]);
    float* dp = &g_ao[((size_t)b * kS + qt * 128 + ty * 4 + i) * kD + h * kDK + tx * 8];
    *(float4*)dp = make_float4(u0.x * inv, u0.y * inv, u1.x * inv, u1.y * inv);
    *(float4*)(dp + 4) = make_float4(u2.x * inv, u2.y * inv, u3.x * inv, u3.y * inv);
  }
}

// ---------------------------------------------------------------------------
// Kernel 3: output projection. [8192,1024] x [1024,1024] -> d_out.
// Same structure as kernel 1. grid = (64 m-tiles, 16 n-tiles)
// ---------------------------------------------------------------------------
__global__ __launch_bounds__(256, 3) void proj_kernel(const float* __restrict__ Wo,
                                                      float* __restrict__ out) {
  __shared__ u64 As2[128 * 34];
  __shared__ float Bs[32 * 72];
  const int m0 = blockIdx.x * 128;
  const int n0 = blockIdx.y * 64;
  const int tid = threadIdx.x;
  const int ty = tid >> 3, tx = tid & 7;

  u64 acc[4][4];
#pragma unroll
  for (int i = 0; i < 4; ++i)
#pragma unroll
    for (int j = 0; j < 4; ++j) acc[i][j] = 0ull;

  for (int d0 = 0; d0 < kD; d0 += 32) {
#pragma unroll
    for (int it = 0; it < 4; ++it) {
      int lin = tid + it * 256;
      int r = lin >> 3, dq = lin & 7;
      float4 v = *(const float4*)&g_ao[(size_t)(m0 + r) * kD + d0 + dq * 4];
      ulonglong2* dst = (ulonglong2*)&As2[r * 34 + dq * 4];
      dst[0] = make_ulonglong2(pack2(v.x, v.x), pack2(v.y, v.y));
      dst[1] = make_ulonglong2(pack2(v.z, v.z), pack2(v.w, v.w));
    }
#pragma unroll
    for (int it = 0; it < 2; ++it) {
      int lin = tid + it * 256;
      int kr = lin >> 4, n4 = lin & 15;
      *(float4*)&Bs[kr * 72 + n4 * 4] =
          *(const float4*)&Wo[(size_t)(d0 + kr) * kD + n0 + n4 * 4];
    }
    __syncthreads();
#pragma unroll 8
    for (int kk = 0; kk < 32; ++kk) {
      ulonglong2 bA = *(const ulonglong2*)&Bs[kk * 72 + tx * 8];
      ulonglong2 bB = *(const ulonglong2*)&Bs[kk * 72 + tx * 8 + 4];
#pragma unroll
      for (int i = 0; i < 4; ++i) {
        u64 aa = As2[(ty * 4 + i) * 34 + kk];
        fma2(acc[i][0], aa, bA.x);
        fma2(acc[i][1], aa, bA.y);
        fma2(acc[i][2], aa, bB.x);
        fma2(acc[i][3], aa, bB.y);
      }
    }
    __syncthreads();
  }
#pragma unroll
  for (int i = 0; i < 4; ++i) {
    float2 u0 = unpack2(acc[i][0]), u1 = unpack2(acc[i][1]);
    float2 u2 = unpack2(acc[i][2]), u3 = unpack2(acc[i][3]);
    float* dp = &out[(size_t)(m0 + ty * 4 + i) * kD + n0 + tx * 8];
    *(float4*)dp = make_float4(u0.x, u0.y, u1.x, u1.y);
    *(float4*)(dp + 4) = make_float4(u2.x, u2.y, u3.x, u3.y);
  }
}

extern "C" void kernel_launch(void* const* d_in, const int* in_sizes, int n_in,
                              void* d_out, int out_size) {
  (void)in_sizes; (void)n_in; (void)out_size;
  const float* x  = (const float*)d_in[0];
  const float* Wq = (const float*)d_in[1];
  const float* Wk = (const float*)d_in[2];
  const float* Wv = (const float*)d_in[3];
  const float* Wo = (const float*)d_in[4];
  float* out = (float*)d_out;

  static int smem_set = 0;
  if (!smem_set) {
    cudaFuncSetAttribute(attn_kernel, cudaFuncAttributeMaxDynamicSharedMemorySize,
                         104448);
    smem_set = 1;
  }

  qkv_kernel<<<dim3(kB * kS / 128, 48), 256>>>(x, Wq, Wk, Wv);
  attn_kernel<<<dim3(kS / 128, kH, kB), 256, 104448>>>();
  proj_kernel<<<dim3(kB * kS / 128, kD / 64), 256>>>(Wo, out);
}

// round 7
// speedup vs baseline: 2.2794x; 2.2794x over previous
#include <cuda_runtime.h>
#include <cuda_bf16.h>

constexpr int kB = 4, kS = 2048, kD = 1024, kH = 16, kDK = 64;
constexpr int kKS = 3072;  // split K dimension [hi | lo | hi]

using u64 = unsigned long long;

// ---------------- f32x2 helpers (attention kernel) ----------------
__device__ __forceinline__ void fma2(u64& d, u64 a, u64 b) {
  asm("fma.rn.f32x2 %0, %1, %2, %0;" : "+l"(d) : "l"(a), "l"(b));
}
__device__ __forceinline__ void mul2(u64& d, u64 a) {
  asm("mul.rn.f32x2 %0, %0, %1;" : "+l"(d) : "l"(a));
}
__device__ __forceinline__ u64 pack2(float x, float y) {
  u64 r; asm("mov.b64 %0, {%1,%2};" : "=l"(r) : "f"(x), "f"(y)); return r;
}
__device__ __forceinline__ float2 unpack2(u64 p) {
  float x, y; asm("mov.b64 {%0,%1}, %2;" : "=f"(x), "=f"(y) : "l"(p));
  return make_float2(x, y);
}

__device__ __forceinline__ unsigned smem_u32(const void* p) {
  unsigned a;
  asm("{ .reg .u64 t; cvta.to.shared.u64 t, %1; cvt.u32.u64 %0, t; }"
      : "=r"(a) : "l"(p));
  return a;
}

// ---------------- mma.sync helpers (sm_80-class PTX) ----------------
__device__ __forceinline__ void cpasync16(unsigned dst, const void* src) {
  asm volatile("cp.async.ca.shared.global [%0], [%1], 16;" :: "r"(dst), "l"(src));
}
__device__ __forceinline__ void ldmx4(unsigned* r, unsigned addr) {
  asm volatile("ldmatrix.sync.aligned.m8n8.x4.shared.b16 {%0,%1,%2,%3}, [%4];"
               : "=r"(r[0]), "=r"(r[1]), "=r"(r[2]), "=r"(r[3]) : "r"(addr));
}
__device__ __forceinline__ void ldmx2(unsigned* r, unsigned addr) {
  asm volatile("ldmatrix.sync.aligned.m8n8.x2.shared.b16 {%0,%1}, [%2];"
               : "=r"(r[0]), "=r"(r[1]) : "r"(addr));
}
__device__ __forceinline__ void mma_bf16(float* d, const unsigned* a,
                                         const unsigned* b) {
  asm volatile(
      "mma.sync.aligned.m16n8k16.row.col.f32.bf16.bf16.f32 "
      "{%0,%1,%2,%3}, {%4,%5,%6,%7}, {%8,%9}, {%0,%1,%2,%3};"
      : "+f"(d[0]), "+f"(d[1]), "+f"(d[2]), "+f"(d[3])
      : "r"(a[0]), "r"(a[1]), "r"(a[2]), "r"(a[3]), "r"(b[0]), "r"(b[1]));
}

// ---------------- scratch ----------------
__device__ __align__(16) float g_q [(size_t)kB * kH * kS * kDK];
__device__ __align__(16) float g_k [(size_t)kB * kH * kS * kDK];
__device__ __align__(16) float g_kt[(size_t)kB * kH * kDK * kS];
__device__ __align__(16) float g_v [(size_t)kB * kH * kS * kDK];
__device__ __align__(16) float g_ao[(size_t)kB * kS * kH * kDK];
__device__ __align__(16) __nv_bfloat16 g_xs [(size_t)kB * kS * kKS];
__device__ __align__(16) __nv_bfloat16 g_ws [(size_t)3 * kH * kDK * kKS];
__device__ __align__(16) __nv_bfloat16 g_wos[(size_t)kD * kKS];
__device__ __align__(16) __nv_bfloat16 g_aos[(size_t)kB * kS * kKS];

__device__ __forceinline__ void split1(float x, unsigned short& h,
                                       unsigned short& l) {
  __nv_bfloat16 hb = __float2bfloat16_rn(x);
  __nv_bfloat16 lb = __float2bfloat16_rn(x - __bfloat162float(hb));
  h = __bfloat16_as_ushort(hb);
  l = __bfloat16_as_ushort(lb);
}

// ---------------- split kernels ----------------
__global__ __launch_bounds__(256) void split_act_kernel(
    const float* __restrict__ src, __nv_bfloat16* __restrict__ dst) {
  const int m = blockIdx.x;
  const int t = threadIdx.x;
  float4 v = *(const float4*)&src[(size_t)m * kD + t * 4];
  unsigned short h[4], l[4];
  split1(v.x, h[0], l[0]); split1(v.y, h[1], l[1]);
  split1(v.z, h[2], l[2]); split1(v.w, h[3], l[3]);
  uint2 hp = make_uint2((unsigned)h[0] | ((unsigned)h[1] << 16),
                        (unsigned)h[2] | ((unsigned)h[3] << 16));
  uint2 lp = make_uint2((unsigned)l[0] | ((unsigned)l[1] << 16),
                        (unsigned)l[2] | ((unsigned)l[3] << 16));
  __nv_bfloat16* base = dst + (size_t)m * kKS;
  *(uint2*)(base + t * 4) = hp;
  *(uint2*)(base + 1024 + t * 4) = lp;
  *(uint2*)(base + 2048 + t * 4) = hp;
}

__global__ __launch_bounds__(256) void split_w_kernel(
    const float* __restrict__ Wq, const float* __restrict__ Wk,
    const float* __restrict__ Wv) {
  const int ng = blockIdx.x;  // 0..3071
  const int mat = ng >> 10;
  const int h = (ng >> 6) & 15;
  const int n = ng & 63;
  const float* W = (mat == 0 ? Wq : (mat == 1 ? Wk : Wv));
  const float* src = W + (size_t)h * kD * kDK + n;
  __nv_bfloat16* dst = g_ws + (size_t)ng * kKS;
#pragma unroll
  for (int it = 0; it < 4; ++it) {
    int d = threadIdx.x + it * 256;
    unsigned short hh, ll;
    split1(src[(size_t)d * kDK], hh, ll);
    dst[d] = __ushort_as_bfloat16(hh);
    dst[1024 + d] = __ushort_as_bfloat16(hh);
    dst[2048 + d] = __ushort_as_bfloat16(ll);
  }
}

__global__ __launch_bounds__(256) void split_wo_kernel(
    const float* __restrict__ Wo) {
  const int n = blockIdx.x;  // 0..1023
  __nv_bfloat16* dst = g_wos + (size_t)n * kKS;
#pragma unroll
  for (int it = 0; it < 4; ++it) {
    int d = threadIdx.x + it * 256;
    unsigned short hh, ll;
    split1(Wo[(size_t)d * kD + n], hh, ll);
    dst[d] = __ushort_as_bfloat16(hh);
    dst[1024 + d] = __ushort_as_bfloat16(hh);
    dst[2048 + d] = __ushort_as_bfloat16(ll);
  }
}

// g_k [bh][s][64] -> g_kt [bh][64][2048]
// NOTE: T stride must keep float4 stores 16B-aligned: 68 * 4 = 272 = 17 * 16.
__global__ __launch_bounds__(256) void transpose_k_kernel() {
  __shared__ float T[64 * 68];
  const int st = blockIdx.x;
  const int bh = blockIdx.y;
  const int tid = threadIdx.x;
  const float* src = g_k + ((size_t)bh * kS + st * 64) * kDK;
#pragma unroll
  for (int it = 0; it < 4; ++it) {
    int lin = tid + it * 256;
    int r = lin >> 4, c4 = lin & 15;
    *(float4*)&T[r * 68 + c4 * 4] = *(const float4*)&src[(size_t)r * kDK + c4 * 4];
  }
  __syncthreads();
  float* dst = g_kt + (size_t)bh * kDK * kS + st * 64;
#pragma unroll
  for (int it = 0; it < 4; ++it) {
    int lin = tid + it * 256;
    int dk = lin >> 4, s4 = lin & 15;
    float4 v = make_float4(T[(s4 * 4 + 0) * 68 + dk], T[(s4 * 4 + 1) * 68 + dk],
                           T[(s4 * 4 + 2) * 68 + dk], T[(s4 * 4 + 3) * 68 + dk]);
    *(float4*)&dst[(size_t)dk * kS + s4 * 4] = v;
  }
}

// ---------------------------------------------------------------------------
// HMMA GEMM: C[128 x 128] = A[128 x 3072] * B[128 x 3072]^T (bf16 -> f32).
// 256 threads = 8 warps (2 M x 4 N), warp tile 64x32, cp.async double buffer.
// mode 0: QKV (B = g_ws panel; out -> g_q/g_k/g_v natural by head)
// mode 1: proj (B = g_wos panel; out -> outP [8192 x 1024])
// Dynamic smem: 4 x 16KB = 65536 B (XOR-swizzled 128B rows).
// ---------------------------------------------------------------------------
__global__ __launch_bounds__(256) void mm_bf16_kernel(
    const __nv_bfloat16* __restrict__ A, const __nv_bfloat16* __restrict__ Bm,
    float* __restrict__ outP, int mode) {
  extern __shared__ char smem[];
  const unsigned sbase = smem_u32(smem);
  const unsigned aA[2] = {sbase, sbase + 16384};
  const unsigned aB[2] = {sbase + 32768, sbase + 49152};

  const int tid = threadIdx.x;
  const int wid = tid >> 5, lane = tid & 31;
  const int m0 = blockIdx.x * 128, n0 = blockIdx.y * 128;
  const int wm = (wid >> 2) * 64, wn = (wid & 3) * 32;
  const __nv_bfloat16* Asrc = A + (size_t)m0 * kKS;
  const __nv_bfloat16* Bsrc = Bm + (size_t)n0 * kKS;

  float acc[4][4][4];
#pragma unroll
  for (int mi = 0; mi < 4; ++mi)
#pragma unroll
    for (int ni = 0; ni < 4; ++ni)
#pragma unroll
      for (int r = 0; r < 4; ++r) acc[mi][ni][r] = 0.f;

#define STAGE(sbuf, ch)                                                        \
  do {                                                                         \
    _Pragma("unroll") for (int i_ = 0; i_ < 4; ++i_) {                         \
      int idx_ = tid + i_ * 256;                                               \
      int r_ = idx_ >> 3, sg_ = idx_ & 7;                                      \
      unsigned sw_ = ((unsigned)(sg_ ^ (r_ & 7))) << 4;                        \
      cpasync16(aA[sbuf] + r_ * 128 + sw_,                                     \
                Asrc + (size_t)r_ * kKS + (ch) * 64 + sg_ * 8);                \
      cpasync16(aB[sbuf] + r_ * 128 + sw_,                                     \
                Bsrc + (size_t)r_ * kKS + (ch) * 64 + sg_ * 8);                \
    }                                                                          \
    asm volatile("cp.async.commit_group;" ::: "memory");                       \
  } while (0)

  STAGE(0, 0);
  for (int ch = 0; ch < kKS / 64; ++ch) {
    const int s = ch & 1;
    if (ch < kKS / 64 - 1) {
      STAGE(s ^ 1, ch + 1);
      asm volatile("cp.async.wait_group 1;" ::: "memory");
    } else {
      asm volatile("cp.async.wait_group 0;" ::: "memory");
    }
    __syncthreads();
#pragma unroll
    for (int ks = 0; ks < 4; ++ks) {
      unsigned af[4][4], bf[4][2];
#pragma unroll
      for (int mi = 0; mi < 4; ++mi) {
        int row = wm + mi * 16 + (lane & 15);
        int cs = ks * 2 + (lane >> 4);
        ldmx4(af[mi], aA[s] + row * 128 + ((unsigned)(cs ^ (row & 7)) << 4));
      }
#pragma unroll
      for (int ni = 0; ni < 4; ++ni) {
        int row = wn + ni * 8 + (lane & 7);
        int cs = ks * 2 + ((lane >> 3) & 1);
        ldmx2(bf[ni], aB[s] + row * 128 + ((unsigned)(cs ^ (row & 7)) << 4));
      }
#pragma unroll
      for (int mi = 0; mi < 4; ++mi)
#pragma unroll
        for (int ni = 0; ni < 4; ++ni) mma_bf16(acc[mi][ni], af[mi], bf[ni]);
    }
    __syncthreads();
  }
#undef STAGE

  const int b = m0 >> 11;
  const int mat = n0 >> 10;
  float* qkvout = (mat == 0 ? g_q : (mat == 1 ? g_k : g_v));
#pragma unroll
  for (int mi = 0; mi < 4; ++mi) {
#pragma unroll
    for (int ni = 0; ni < 4; ++ni) {
      int rl = wm + mi * 16 + (lane >> 2);
      int n = n0 + wn + ni * 8 + (lane & 3) * 2;
      if (mode == 0) {
        int h = (n >> 6) & 15, dk = n & 63;
        size_t rowbase = (size_t)(b * kH + h) * kS + (m0 & (kS - 1));
        *(float2*)&qkvout[(rowbase + rl) * kDK + dk] =
            make_float2(acc[mi][ni][0], acc[mi][ni][1]);
        *(float2*)&qkvout[(rowbase + rl + 8) * kDK + dk] =
            make_float2(acc[mi][ni][2], acc[mi][ni][3]);
      } else {
        int m = m0 + rl;
        *(float2*)&outP[(size_t)m * kD + n] =
            make_float2(acc[mi][ni][0], acc[mi][ni][1]);
        *(float2*)&outP[(size_t)(m + 8) * kD + n] =
            make_float2(acc[mi][ni][2], acc[mi][ni][3]);
      }
    }
  }
}

// ---------------------------------------------------------------------------
// Fused flash attention (R3 design, best measured): 128q-tile, 64k K-tiles,
// 128 threads, 8q x 8dv per thread, f32x2 MACs, register P via shfl.
// Dynamic smem: Qs[128][68] + Ks[64][72] + Vs[64][72] = 71680 B.
// ---------------------------------------------------------------------------
__global__ __launch_bounds__(128, 2) void attn_kernel() {
  extern __shared__ float smf[];
  float* Qs = smf;
  float* Ks = smf + 128 * 68;
  float* Vs = Ks + 64 * 72;
  const int qt = blockIdx.x, h = blockIdx.y, b = blockIdx.z;
  const int bh = b * kH + h;
  const int tid = threadIdx.x;
  const int ty = tid >> 3, tx = tid & 7;
  const int lane = tid & 31;

  const float* qsrc = g_q + ((size_t)bh * kS + qt * 128) * kDK;
#pragma unroll
  for (int it = 0; it < 16; ++it) {
    int lin = tid + it * 128;
    int r = lin >> 4, dq = lin & 15;
    float4 v = *(const float4*)&qsrc[(size_t)r * kDK + dq * 4];
    v.x *= 0.125f; v.y *= 0.125f; v.z *= 0.125f; v.w *= 0.125f;
    *(float4*)&Qs[r * 68 + dq * 4] = v;
  }

  u64 o2[8][4];
  float m_[8], l_[8];
#pragma unroll
  for (int i = 0; i < 8; ++i) {
    m_[i] = -3.0e38f;
    l_[i] = 0.f;
#pragma unroll
    for (int j = 0; j < 4; ++j) o2[i][j] = 0ull;
  }

  const float* ktbase = g_kt + (size_t)bh * kDK * kS;
  const float* vbase = g_v + (size_t)bh * kS * kDK;

  for (int kt = 0; kt < kS / 64; ++kt) {
#pragma unroll
    for (int it = 0; it < 8; ++it) {
      int lin = tid + it * 128;
      int dd = lin >> 4, c4 = lin & 15;
      *(float4*)&Ks[dd * 72 + c4 * 4] =
          *(const float4*)&ktbase[(size_t)dd * kS + kt * 64 + c4 * 4];
    }
#pragma unroll
    for (int it = 0; it < 8; ++it) {
      int lin = tid + it * 128;
      int c = lin >> 4, dq = lin & 15;
      *(float4*)&Vs[c * 72 + dq * 4] =
          *(const float4*)&vbase[(size_t)(kt * 64 + c) * kDK + dq * 4];
    }
    __syncthreads();

    u64 s2[8][4];
#pragma unroll
    for (int i = 0; i < 8; ++i)
#pragma unroll
      for (int j = 0; j < 4; ++j) s2[i][j] = 0ull;
#pragma unroll 8
    for (int kk = 0; kk < 64; ++kk) {
      ulonglong2 bA = *(const ulonglong2*)&Ks[kk * 72 + tx * 8];
      ulonglong2 bB = *(const ulonglong2*)&Ks[kk * 72 + tx * 8 + 4];
#pragma unroll
      for (int i = 0; i < 8; ++i) {
        float qv = Qs[(ty * 8 + i) * 68 + kk];
        u64 aa = pack2(qv, qv);
        fma2(s2[i][0], aa, bA.x);
        fma2(s2[i][1], aa, bA.y);
        fma2(s2[i][2], aa, bB.x);
        fma2(s2[i][3], aa, bB.y);
      }
    }

    float sp[8][8];
#pragma unroll
    for (int i = 0; i < 8; ++i) {
      float2 u0 = unpack2(s2[i][0]), u1 = unpack2(s2[i][1]);
      float2 u2 = unpack2(s2[i][2]), u3 = unpack2(s2[i][3]);
      float sc[8] = {u0.x, u0.y, u1.x, u1.y, u2.x, u2.y, u3.x, u3.y};
      float mx = fmaxf(fmaxf(fmaxf(sc[0], sc[1]), fmaxf(sc[2], sc[3])),
                       fmaxf(fmaxf(sc[4], sc[5]), fmaxf(sc[6], sc[7])));
      mx = fmaxf(mx, __shfl_xor_sync(0xffffffffu, mx, 1));
      mx = fmaxf(mx, __shfl_xor_sync(0xffffffffu, mx, 2));
      mx = fmaxf(mx, __shfl_xor_sync(0xffffffffu, mx, 4));
      float mnew = fmaxf(m_[i], mx);
      float corr = __expf(m_[i] - mnew);
      m_[i] = mnew;
      float sum = 0.f;
#pragma unroll
      for (int j = 0; j < 8; ++j) {
        sc[j] = __expf(sc[j] - mnew);
        sum += sc[j];
        sp[i][j] = sc[j];
      }
      sum += __shfl_xor_sync(0xffffffffu, sum, 1);
      sum += __shfl_xor_sync(0xffffffffu, sum, 2);
      sum += __shfl_xor_sync(0xffffffffu, sum, 4);
      l_[i] = l_[i] * corr + sum;
      u64 cc = pack2(corr, corr);
      mul2(o2[i][0], cc); mul2(o2[i][1], cc);
      mul2(o2[i][2], cc); mul2(o2[i][3], cc);
    }

    for (int ct = 0; ct < 8; ++ct) {
      int src = (lane & 24) | ct;
#pragma unroll
      for (int ci = 0; ci < 8; ++ci) {
        int c = ct * 8 + ci;
        ulonglong2 vA = *(const ulonglong2*)&Vs[c * 72 + tx * 8];
        ulonglong2 vB = *(const ulonglong2*)&Vs[c * 72 + tx * 8 + 4];
#pragma unroll
        for (int i = 0; i < 8; ++i) {
          float p = __shfl_sync(0xffffffffu, sp[i][ci], src);
          u64 pp = pack2(p, p);
          fma2(o2[i][0], pp, vA.x);
          fma2(o2[i][1], pp, vA.y);
          fma2(o2[i][2], pp, vB.x);
          fma2(o2[i][3], pp, vB.y);
        }
      }
    }
    __syncthreads();
  }

#pragma unroll
  for (int i = 0; i < 8; ++i) {
    float inv = 1.f / l_[i];
    float2 u0 = unpack2(o2[i][0]), u1 = unpack2(o2[i][1]);
    float2 u2 = unpack2(o2[i][2]), u3 = unpack2(o2[i][3]);
    float* dp = &g_ao[((size_t)b * kS + qt * 128 + ty * 8 + i) * kD + h * kDK + tx * 8];
    *(float4*)dp = make_float4(u0.x * inv, u0.y * inv, u1.x * inv, u1.y * inv);
    *(float4*)(dp + 4) = make_float4(u2.x * inv, u2.y * inv, u3.x * inv, u3.y * inv);
  }
}

// ---------------------------------------------------------------------------
extern "C" void kernel_launch(void* const* d_in, const int* in_sizes, int n_in,
                              void* d_out, int out_size) {
  (void)in_sizes; (void)n_in; (void)out_size;
  const float* x  = (const float*)d_in[0];
  const float* Wq = (const float*)d_in[1];
  const float* Wk = (const float*)d_in[2];
  const float* Wv = (const float*)d_in[3];
  const float* Wo = (const float*)d_in[4];
  float* out = (float*)d_out;

  static int attr_set = 0;
  if (!attr_set) {
    cudaFuncSetAttribute(attn_kernel, cudaFuncAttributeMaxDynamicSharedMemorySize,
                         71680);
    cudaFuncSetAttribute(mm_bf16_kernel,
                         cudaFuncAttributeMaxDynamicSharedMemorySize, 65536);
    attr_set = 1;
  }

  __nv_bfloat16* xs;  cudaGetSymbolAddress((void**)&xs, g_xs);
  __nv_bfloat16* ws;  cudaGetSymbolAddress((void**)&ws, g_ws);
  __nv_bfloat16* wos; cudaGetSymbolAddress((void**)&wos, g_wos);
  __nv_bfloat16* aos; cudaGetSymbolAddress((void**)&aos, g_aos);
  float* aop;         cudaGetSymbolAddress((void**)&aop, g_ao);

  split_act_kernel<<<kB * kS, 256>>>(x, xs);
  split_w_kernel<<<3 * kH * kDK, 256>>>(Wq, Wk, Wv);
  split_wo_kernel<<<kD, 256>>>(Wo);
  mm_bf16_kernel<<<dim3(kB * kS / 128, kKS / 128), 256, 65536>>>(xs, ws, nullptr, 0);
  transpose_k_kernel<<<dim3(kS / 64, kB * kH), 256>>>();
  attn_kernel<<<dim3(kS / 128, kH, kB), 128, 71680>>>();
  split_act_kernel<<<kB * kS, 256>>>(aop, aos);
  mm_bf16_kernel<<<dim3(kB * kS / 128, kD / 128), 256, 65536>>>(aos, wos, out, 1);
}

// round 8
// speedup vs baseline: 4.6829x; 2.0544x over previous
#include <cuda_runtime.h>
#include <cuda_bf16.h>

constexpr int kB = 4, kS = 2048, kD = 1024, kH = 16, kDK = 64;
constexpr int kKS = 3072;  // split K dimension [hi | lo | hi]
constexpr int kCap = 32;   // shortlist capacity per row

__device__ __forceinline__ unsigned smem_u32(const void* p) {
  unsigned a;
  asm("{ .reg .u64 t; cvta.to.shared.u64 t, %1; cvt.u32.u64 %0, t; }"
      : "=r"(a) : "l"(p));
  return a;
}

// ---------------- mma.sync helpers (sm_80-class PTX) ----------------
__device__ __forceinline__ void cpasync16(unsigned dst, const void* src) {
  asm volatile("cp.async.ca.shared.global [%0], [%1], 16;" :: "r"(dst), "l"(src));
}
__device__ __forceinline__ void ldmx4(unsigned* r, unsigned addr) {
  asm volatile("ldmatrix.sync.aligned.m8n8.x4.shared.b16 {%0,%1,%2,%3}, [%4];"
               : "=r"(r[0]), "=r"(r[1]), "=r"(r[2]), "=r"(r[3]) : "r"(addr));
}
__device__ __forceinline__ void ldmx2(unsigned* r, unsigned addr) {
  asm volatile("ldmatrix.sync.aligned.m8n8.x2.shared.b16 {%0,%1}, [%2];"
               : "=r"(r[0]), "=r"(r[1]) : "r"(addr));
}
__device__ __forceinline__ void mma_bf16(float* d, const unsigned* a,
                                         const unsigned* b) {
  asm volatile(
      "mma.sync.aligned.m16n8k16.row.col.f32.bf16.bf16.f32 "
      "{%0,%1,%2,%3}, {%4,%5,%6,%7}, {%8,%9}, {%0,%1,%2,%3};"
      : "+f"(d[0]), "+f"(d[1]), "+f"(d[2]), "+f"(d[3])
      : "r"(a[0]), "r"(a[1]), "r"(a[2]), "r"(a[3]), "r"(b[0]), "r"(b[1]));
}

// ---------------- scratch ----------------
__device__ __align__(16) float g_q [(size_t)kB * kH * kS * kDK];
__device__ __align__(16) float g_k [(size_t)kB * kH * kS * kDK];
__device__ __align__(16) float g_v [(size_t)kB * kH * kS * kDK];
__device__ __align__(16) float g_ao[(size_t)kB * kS * kH * kDK];
__device__ __align__(16) __nv_bfloat16 g_xs [(size_t)kB * kS * kKS];
__device__ __align__(16) __nv_bfloat16 g_ws [(size_t)3 * kH * kDK * kKS];
__device__ __align__(16) __nv_bfloat16 g_wos[(size_t)kD * kKS];
__device__ __align__(16) __nv_bfloat16 g_aos[(size_t)kB * kS * kKS];
__device__ int            g_cnt [(size_t)kB * kH * kS];
__device__ unsigned short g_slot[(size_t)kB * kH * kS * kCap];

__device__ __forceinline__ void split1(float x, unsigned short& h,
                                       unsigned short& l) {
  __nv_bfloat16 hb = __float2bfloat16_rn(x);
  __nv_bfloat16 lb = __float2bfloat16_rn(x - __bfloat162float(hb));
  h = __bfloat16_as_ushort(hb);
  l = __bfloat16_as_ushort(lb);
}

// split 8 consecutive floats into packed bf16 hi/lo uint4's
__device__ __forceinline__ void split8(const float* v, uint4& hi, uint4& lo) {
  unsigned short h[8], l[8];
#pragma unroll
  for (int j = 0; j < 8; ++j) split1(v[j], h[j], l[j]);
  hi = make_uint4((unsigned)h[0] | ((unsigned)h[1] << 16),
                  (unsigned)h[2] | ((unsigned)h[3] << 16),
                  (unsigned)h[4] | ((unsigned)h[5] << 16),
                  (unsigned)h[6] | ((unsigned)h[7] << 16));
  lo = make_uint4((unsigned)l[0] | ((unsigned)l[1] << 16),
                  (unsigned)l[2] | ((unsigned)l[3] << 16),
                  (unsigned)l[4] | ((unsigned)l[5] << 16),
                  (unsigned)l[6] | ((unsigned)l[7] << 16));
}

// ---------------- split kernels (unchanged from R7) ----------------
__global__ __launch_bounds__(256) void split_act_kernel(
    const float* __restrict__ src, __nv_bfloat16* __restrict__ dst) {
  const int m = blockIdx.x;
  const int t = threadIdx.x;
  float4 v = *(const float4*)&src[(size_t)m * kD + t * 4];
  unsigned short h[4], l[4];
  split1(v.x, h[0], l[0]); split1(v.y, h[1], l[1]);
  split1(v.z, h[2], l[2]); split1(v.w, h[3], l[3]);
  uint2 hp = make_uint2((unsigned)h[0] | ((unsigned)h[1] << 16),
                        (unsigned)h[2] | ((unsigned)h[3] << 16));
  uint2 lp = make_uint2((unsigned)l[0] | ((unsigned)l[1] << 16),
                        (unsigned)l[2] | ((unsigned)l[3] << 16));
  __nv_bfloat16* base = dst + (size_t)m * kKS;
  *(uint2*)(base + t * 4) = hp;
  *(uint2*)(base + 1024 + t * 4) = lp;
  *(uint2*)(base + 2048 + t * 4) = hp;
}

__global__ __launch_bounds__(256) void split_w_kernel(
    const float* __restrict__ Wq, const float* __restrict__ Wk,
    const float* __restrict__ Wv) {
  const int ng = blockIdx.x;
  const int mat = ng >> 10;
  const int h = (ng >> 6) & 15;
  const int n = ng & 63;
  const float* W = (mat == 0 ? Wq : (mat == 1 ? Wk : Wv));
  const float* src = W + (size_t)h * kD * kDK + n;
  __nv_bfloat16* dst = g_ws + (size_t)ng * kKS;
#pragma unroll
  for (int it = 0; it < 4; ++it) {
    int d = threadIdx.x + it * 256;
    unsigned short hh, ll;
    split1(src[(size_t)d * kDK], hh, ll);
    dst[d] = __ushort_as_bfloat16(hh);
    dst[1024 + d] = __ushort_as_bfloat16(hh);
    dst[2048 + d] = __ushort_as_bfloat16(ll);
  }
}

__global__ __launch_bounds__(256) void split_wo_kernel(
    const float* __restrict__ Wo) {
  const int n = blockIdx.x;
  __nv_bfloat16* dst = g_wos + (size_t)n * kKS;
#pragma unroll
  for (int it = 0; it < 4; ++it) {
    int d = threadIdx.x + it * 256;
    unsigned short hh, ll;
    split1(Wo[(size_t)d * kD + n], hh, ll);
    dst[d] = __ushort_as_bfloat16(hh);
    dst[1024 + d] = __ushort_as_bfloat16(hh);
    dst[2048 + d] = __ushort_as_bfloat16(ll);
  }
}

// ---------------------------------------------------------------------------
// HMMA GEMM (unchanged, proven in R7).
// ---------------------------------------------------------------------------
__global__ __launch_bounds__(256) void mm_bf16_kernel(
    const __nv_bfloat16* __restrict__ A, const __nv_bfloat16* __restrict__ Bm,
    float* __restrict__ outP, int mode) {
  extern __shared__ char smem[];
  const unsigned sbase = smem_u32(smem);
  const unsigned aA[2] = {sbase, sbase + 16384};
  const unsigned aB[2] = {sbase + 32768, sbase + 49152};

  const int tid = threadIdx.x;
  const int wid = tid >> 5, lane = tid & 31;
  const int m0 = blockIdx.x * 128, n0 = blockIdx.y * 128;
  const int wm = (wid >> 2) * 64, wn = (wid & 3) * 32;
  const __nv_bfloat16* Asrc = A + (size_t)m0 * kKS;
  const __nv_bfloat16* Bsrc = Bm + (size_t)n0 * kKS;

  float acc[4][4][4];
#pragma unroll
  for (int mi = 0; mi < 4; ++mi)
#pragma unroll
    for (int ni = 0; ni < 4; ++ni)
#pragma unroll
      for (int r = 0; r < 4; ++r) acc[mi][ni][r] = 0.f;

#define STAGE(sbuf, ch)                                                        \
  do {                                                                         \
    _Pragma("unroll") for (int i_ = 0; i_ < 4; ++i_) {                         \
      int idx_ = tid + i_ * 256;                                               \
      int r_ = idx_ >> 3, sg_ = idx_ & 7;                                      \
      unsigned sw_ = ((unsigned)(sg_ ^ (r_ & 7))) << 4;                        \
      cpasync16(aA[sbuf] + r_ * 128 + sw_,                                     \
                Asrc + (size_t)r_ * kKS + (ch) * 64 + sg_ * 8);                \
      cpasync16(aB[sbuf] + r_ * 128 + sw_,                                     \
                Bsrc + (size_t)r_ * kKS + (ch) * 64 + sg_ * 8);                \
    }                                                                          \
    asm volatile("cp.async.commit_group;" ::: "memory");                       \
  } while (0)

  STAGE(0, 0);
  for (int ch = 0; ch < kKS / 64; ++ch) {
    const int s = ch & 1;
    if (ch < kKS / 64 - 1) {
      STAGE(s ^ 1, ch + 1);
      asm volatile("cp.async.wait_group 1;" ::: "memory");
    } else {
      asm volatile("cp.async.wait_group 0;" ::: "memory");
    }
    __syncthreads();
#pragma unroll
    for (int ks = 0; ks < 4; ++ks) {
      unsigned af[4][4], bf[4][2];
#pragma unroll
      for (int mi = 0; mi < 4; ++mi) {
        int row = wm + mi * 16 + (lane & 15);
        int cs = ks * 2 + (lane >> 4);
        ldmx4(af[mi], aA[s] + row * 128 + ((unsigned)(cs ^ (row & 7)) << 4));
      }
#pragma unroll
      for (int ni = 0; ni < 4; ++ni) {
        int row = wn + ni * 8 + (lane & 7);
        int cs = ks * 2 + ((lane >> 3) & 1);
        ldmx2(bf[ni], aB[s] + row * 128 + ((unsigned)(cs ^ (row & 7)) << 4));
      }
#pragma unroll
      for (int mi = 0; mi < 4; ++mi)
#pragma unroll
        for (int ni = 0; ni < 4; ++ni) mma_bf16(acc[mi][ni], af[mi], bf[ni]);
    }
    __syncthreads();
  }
#undef STAGE

  const int b = m0 >> 11;
  const int mat = n0 >> 10;
  float* qkvout = (mat == 0 ? g_q : (mat == 1 ? g_k : g_v));
#pragma unroll
  for (int mi = 0; mi < 4; ++mi) {
#pragma unroll
    for (int ni = 0; ni < 4; ++ni) {
      int rl = wm + mi * 16 + (lane >> 2);
      int n = n0 + wn + ni * 8 + (lane & 3) * 2;
      if (mode == 0) {
        int h = (n >> 6) & 15, dk = n & 63;
        size_t rowbase = (size_t)(b * kH + h) * kS + (m0 & (kS - 1));
        *(float2*)&qkvout[(rowbase + rl) * kDK + dk] =
            make_float2(acc[mi][ni][0], acc[mi][ni][1]);
        *(float2*)&qkvout[(rowbase + rl + 8) * kDK + dk] =
            make_float2(acc[mi][ni][2], acc[mi][ni][3]);
      } else {
        int m = m0 + rl;
        *(float2*)&outP[(size_t)m * kD + n] =
            make_float2(acc[mi][ni][0], acc[mi][ni][1]);
        *(float2*)&outP[(size_t)(m + 8) * kD + n] =
            make_float2(acc[mi][ni][2], acc[mi][ni][3]);
      }
    }
  }
}

// ---------------------------------------------------------------------------
// attn_smax: S = QK^T via HMMA (bf16 split), online row max + shortlist.
// block = (qtile 128, head, batch), 256 thr = 8 warps, warp tile 16q x 128t.
// smem: Qhi/Qlo/Khi/Klo 16KB each + cnt 512B + slots 8KB = 74240 B.
// ---------------------------------------------------------------------------
__global__ __launch_bounds__(256) void attn_smax_kernel() {
  extern __shared__ char sm[];
  const unsigned sb = smem_u32(sm);
  const unsigned aQhi = sb, aQlo = sb + 16384;
  const unsigned aKhi = sb + 32768, aKlo = sb + 49152;
  int* scnt = (int*)(sm + 65536);
  unsigned short* stid = (unsigned short*)(sm + 66048);

  const int tid = threadIdx.x;
  const int warp = tid >> 5, lane = tid & 31;
  const int qt = blockIdx.x, h = blockIdx.y, b = blockIdx.z;
  const int bh = b * kH + h;

  if (tid < 128) scnt[tid] = 0;

  // load + split Q tile (scale 1/8 folded in)
  const float* qsrc = g_q + ((size_t)bh * kS + qt * 128) * kDK;
#pragma unroll
  for (int it = 0; it < 4; ++it) {
    int idx = tid + it * 256;
    int row = idx >> 3, g = idx & 7;
    float v[8];
    float4 v0 = *(const float4*)&qsrc[(size_t)row * kDK + g * 8];
    float4 v1 = *(const float4*)&qsrc[(size_t)row * kDK + g * 8 + 4];
    v[0] = v0.x * 0.125f; v[1] = v0.y * 0.125f; v[2] = v0.z * 0.125f;
    v[3] = v0.w * 0.125f; v[4] = v1.x * 0.125f; v[5] = v1.y * 0.125f;
    v[6] = v1.z * 0.125f; v[7] = v1.w * 0.125f;
    uint4 hi, lo;
    split8(v, hi, lo);
    unsigned sw = ((unsigned)(g ^ (row & 7))) << 4;
    *(uint4*)(sm + row * 128 + sw) = hi;
    *(uint4*)(sm + 16384 + row * 128 + sw) = lo;
  }

  float m0 = -3.0e38f, m1 = -3.0e38f;
  const int r0 = (warp << 4) + (lane >> 2);

  for (int kt = 0; kt < kS / 128; ++kt) {
    // load + split K tile
    const float* ksrc = g_k + ((size_t)bh * kS + kt * 128) * kDK;
#pragma unroll
    for (int it = 0; it < 4; ++it) {
      int idx = tid + it * 256;
      int row = idx >> 3, g = idx & 7;
      float v[8];
      float4 v0 = *(const float4*)&ksrc[(size_t)row * kDK + g * 8];
      float4 v1 = *(const float4*)&ksrc[(size_t)row * kDK + g * 8 + 4];
      v[0] = v0.x; v[1] = v0.y; v[2] = v0.z; v[3] = v0.w;
      v[4] = v1.x; v[5] = v1.y; v[6] = v1.z; v[7] = v1.w;
      uint4 hi, lo;
      split8(v, hi, lo);
      unsigned sw = ((unsigned)(g ^ (row & 7))) << 4;
      *(uint4*)(sm + 32768 + row * 128 + sw) = hi;
      *(uint4*)(sm + 49152 + row * 128 + sw) = lo;
    }
    __syncthreads();

    float acc[16][4];
#pragma unroll
    for (int tt = 0; tt < 16; ++tt)
#pragma unroll
      for (int j = 0; j < 4; ++j) acc[tt][j] = 0.f;

#pragma unroll
    for (int kc = 0; kc < 4; ++kc) {
      unsigned aHi[4], aLo[4];
      int rowq = (warp << 4) + (lane & 15);
      int cs = kc * 2 + (lane >> 4);
      unsigned swq = ((unsigned)(cs ^ (rowq & 7))) << 4;
      ldmx4(aHi, aQhi + rowq * 128 + swq);
      ldmx4(aLo, aQlo + rowq * 128 + swq);
#pragma unroll
      for (int tt = 0; tt < 16; ++tt) {
        int rowb = tt * 8 + (lane & 7);
        int csb = kc * 2 + ((lane >> 3) & 1);
        unsigned swb = ((unsigned)(csb ^ (rowb & 7))) << 4;
        unsigned bh2[2], bl2[2];
        ldmx2(bh2, aKhi + rowb * 128 + swb);
        mma_bf16(acc[tt], aHi, bh2);
        mma_bf16(acc[tt], aLo, bh2);
        ldmx2(bl2, aKlo + rowb * 128 + swb);
        mma_bf16(acc[tt], aHi, bl2);
      }
    }

    // update running row max (quad reduce over cols)
    float lm0 = -3.0e38f, lm1 = -3.0e38f;
#pragma unroll
    for (int tt = 0; tt < 16; ++tt) {
      lm0 = fmaxf(lm0, fmaxf(acc[tt][0], acc[tt][1]));
      lm1 = fmaxf(lm1, fmaxf(acc[tt][2], acc[tt][3]));
    }
    lm0 = fmaxf(lm0, __shfl_xor_sync(0xffffffffu, lm0, 1));
    lm0 = fmaxf(lm0, __shfl_xor_sync(0xffffffffu, lm0, 2));
    lm1 = fmaxf(lm1, __shfl_xor_sync(0xffffffffu, lm1, 1));
    lm1 = fmaxf(lm1, __shfl_xor_sync(0xffffffffu, lm1, 2));
    m0 = fmaxf(m0, lm0);
    m1 = fmaxf(m1, lm1);

    // shortlist insertion (threshold vs running max: only over-includes)
    float th0 = m0 - 46.f, th1 = m1 - 46.f;
#pragma unroll
    for (int tt = 0; tt < 16; ++tt) {
      int tb = kt * 128 + tt * 8 + (lane & 3) * 2;
      if (acc[tt][0] > th0) {
        int i = atomicAdd(&scnt[r0], 1);
        if (i < kCap) stid[r0 * kCap + i] = (unsigned short)tb;
      }
      if (acc[tt][1] > th0) {
        int i = atomicAdd(&scnt[r0], 1);
        if (i < kCap) stid[r0 * kCap + i] = (unsigned short)(tb + 1);
      }
      if (acc[tt][2] > th1) {
        int i = atomicAdd(&scnt[r0 + 8], 1);
        if (i < kCap) stid[(r0 + 8) * kCap + i] = (unsigned short)tb;
      }
      if (acc[tt][3] > th1) {
        int i = atomicAdd(&scnt[r0 + 8], 1);
        if (i < kCap) stid[(r0 + 8) * kCap + i] = (unsigned short)(tb + 1);
      }
    }
    __syncthreads();  // done with K tile before overwrite
  }

  if (tid < 128) {
    size_t row_g = ((size_t)bh * 16 + qt) * 128 + tid;
    int c = scnt[tid];
    g_cnt[row_g] = c;
    int cc = c < kCap ? c : kCap;
    for (int i = 0; i < cc; ++i) g_slot[row_g * kCap + i] = stid[tid * kCap + i];
  }
}

// ---------------------------------------------------------------------------
// attn_gather: warp per q-row; exact fp32 softmax over shortlist; gather V.
// ---------------------------------------------------------------------------
__global__ __launch_bounds__(256) void attn_gather_kernel() {
  const int warp = threadIdx.x >> 5, lane = threadIdx.x & 31;
  const size_t row_g = (size_t)blockIdx.x * 8 + warp;
  const int qrow = (int)(row_g & 127);
  const int qt = (int)((row_g >> 7) & 15);
  const int h = (int)((row_g >> 11) & 15);
  const int b = (int)(row_g >> 15);
  const int bh = b * kH + h;
  const int sq = qt * 128 + qrow;

  const float* qp = g_q + ((size_t)bh * kS + sq) * kDK;
  const float* kb = g_k + (size_t)bh * kS * kDK;
  const float* vb = g_v + (size_t)bh * kS * kDK;
  float* outp = g_ao + ((size_t)b * kS + sq) * kD + h * kDK;

  const float q0 = qp[lane] * 0.125f, q1 = qp[lane + 32] * 0.125f;
  const int cnt = g_cnt[row_g];

  float m = -3.0e38f, l = 0.f, a0 = 0.f, a1 = 0.f;
  if (cnt <= kCap) {
    const unsigned short* sl = g_slot + row_g * kCap;
    // pass 1: exact row max over shortlist
    for (int i = 0; i < cnt; ++i) {
      int t = sl[i];
      float d = q0 * kb[(size_t)t * kDK + lane] + q1 * kb[(size_t)t * kDK + lane + 32];
#pragma unroll
      for (int o = 16; o > 0; o >>= 1) d += __shfl_xor_sync(0xffffffffu, d, o);
      m = fmaxf(m, d);
    }
    // pass 2: exact softmax + V gather
    for (int i = 0; i < cnt; ++i) {
      int t = sl[i];
      float d = q0 * kb[(size_t)t * kDK + lane] + q1 * kb[(size_t)t * kDK + lane + 32];
#pragma unroll
      for (int o = 16; o > 0; o >>= 1) d += __shfl_xor_sync(0xffffffffu, d, o);
      float p = __expf(d - m);
      l += p;
      a0 += p * vb[(size_t)t * kDK + lane];
      a1 += p * vb[(size_t)t * kDK + lane + 32];
    }
  } else {
    // fallback: full online softmax over all 2048 keys (rare)
    for (int t = 0; t < kS; ++t) {
      float d = q0 * kb[(size_t)t * kDK + lane] + q1 * kb[(size_t)t * kDK + lane + 32];
#pragma unroll
      for (int o = 16; o > 0; o >>= 1) d += __shfl_xor_sync(0xffffffffu, d, o);
      float v0 = vb[(size_t)t * kDK + lane], v1 = vb[(size_t)t * kDK + lane + 32];
      if (d > m) {
        float c = __expf(m - d);
        m = d;
        l = l * c + 1.f;
        a0 = a0 * c + v0;
        a1 = a1 * c + v1;
      } else {
        float p = __expf(d - m);
        l += p;
        a0 += p * v0;
        a1 += p * v1;
      }
    }
  }
  float inv = 1.f / l;
  outp[lane] = a0 * inv;
  outp[lane + 32] = a1 * inv;
}

// ---------------------------------------------------------------------------
extern "C" void kernel_launch(void* const* d_in, const int* in_sizes, int n_in,
                              void* d_out, int out_size) {
  (void)in_sizes; (void)n_in; (void)out_size;
  const float* x  = (const float*)d_in[0];
  const float* Wq = (const float*)d_in[1];
  const float* Wk = (const float*)d_in[2];
  const float* Wv = (const float*)d_in[3];
  const float* Wo = (const float*)d_in[4];
  float* out = (float*)d_out;

  static int attr_set = 0;
  if (!attr_set) {
    cudaFuncSetAttribute(mm_bf16_kernel,
                         cudaFuncAttributeMaxDynamicSharedMemorySize, 65536);
    cudaFuncSetAttribute(attn_smax_kernel,
                         cudaFuncAttributeMaxDynamicSharedMemorySize, 74240);
    attr_set = 1;
  }

  __nv_bfloat16* xs;  cudaGetSymbolAddress((void**)&xs, g_xs);
  __nv_bfloat16* ws;  cudaGetSymbolAddress((void**)&ws, g_ws);
  __nv_bfloat16* wos; cudaGetSymbolAddress((void**)&wos, g_wos);
  __nv_bfloat16* aos; cudaGetSymbolAddress((void**)&aos, g_aos);
  float* aop;         cudaGetSymbolAddress((void**)&aop, g_ao);

  split_act_kernel<<<kB * kS, 256>>>(x, xs);
  split_w_kernel<<<3 * kH * kDK, 256>>>(Wq, Wk, Wv);
  split_wo_kernel<<<kD, 256>>>(Wo);
  mm_bf16_kernel<<<dim3(kB * kS / 128, kKS / 128), 256, 65536>>>(xs, ws, nullptr, 0);
  attn_smax_kernel<<<dim3(kS / 128, kH, kB), 256, 74240>>>();
  attn_gather_kernel<<<kB * kH * kS / 8, 256>>>();
  split_act_kernel<<<kB * kS, 256>>>(aop, aos);
  mm_bf16_kernel<<<dim3(kB * kS / 128, kD / 128), 256, 65536>>>(aos, wos, out, 1);
}